// round 11
// baseline (speedup 1.0000x reference)
#include <cuda_runtime.h>
#include <cstdint>

// ---------------------------------------------------------------------------
// Problem constants
// ---------------------------------------------------------------------------
#define BATCH 64
#define SEQ   512
#define DIM   768
#define BD    (BATCH * DIM)          // 49152
#define R192  192
#define KDIM  1536
#define PREDK 2304

#define KS_FC1  12                   // 1536 = 12 * 128
#define KS_PRED 12                   // 2304 = 12 * 192
// gate: KS=4, z=0..2 stored as partials, z=3 fused consumer
#define GATE_TILES 36                // 3 m-tiles x 12 n-tiles

#define FC1_MN  (R192 * 512)         // 98304
#define GATE_MN (R192 * 768)         // 147456
#define PRED_MN (BATCH * 512)        // 32768

// smem: per worker 2 stages x (As[32][72] + Bs[32][72]) in floats
#define AS_PITCH 72
#define AS_F     (32 * AS_PITCH)     // 2304
#define BS_F     (32 * AS_PITCH)     // 2304
#define STAGE_F  (AS_F + BS_F)       // 4608
#define WORKER_F (2 * STAGE_F)       // 9216
#define TOTAL_SMEM_B (2 * WORKER_F * 4)   // 73728 bytes

// ---------------------------------------------------------------------------
// Device scratch
// ---------------------------------------------------------------------------
__device__ float g_ent  [BATCH * PREDK];
__device__ float g_e    [3 * BD];              // entity state [r][d], r=k*64+b
__device__ float g_X1   [R192 * KDIM];         // fc1 input  [eA | eB]
__device__ float g_X2   [R192 * KDIM];         // gate input [u  | e ]
__device__ float g_mp   [768 * DIM];           // maxpool segment partials
__device__ float g_pfc1 [KS_FC1 * FC1_MN];
__device__ float g_pgate[3 * GATE_MN];         // gate partials z=0..2
__device__ float g_ppred[KS_PRED * PRED_MN];

__device__ unsigned int g_gcnt[GATE_TILES];    // per-tile arrival counters
__device__ unsigned int g_bar_count = 0;
__device__ unsigned int g_bar_gen   = 0;

// ---------------------------------------------------------------------------
// Helpers
// ---------------------------------------------------------------------------
__device__ __forceinline__ float sigmoidf(float x) {
    return 1.0f / (1.0f + expf(-x));
}
__device__ __forceinline__ float4 ldcg4(const float* p) {
    return __ldcg(reinterpret_cast<const float4*>(p));
}
__device__ __forceinline__ float2 ldcg2(const float* p) {
    return __ldcg(reinterpret_cast<const float2*>(p));
}
__device__ __forceinline__ void stcg4(float* p, float4 v) {
    __stcg(reinterpret_cast<float4*>(p), v);
}
__device__ __forceinline__ void stcg2(float* p, float2 v) {
    __stcg(reinterpret_cast<float2*>(p), v);
}
__device__ __forceinline__ float4 ldg4(const float* p) {
    return __ldg(reinterpret_cast<const float4*>(p));
}
__device__ __forceinline__ float2 ldg2(const float* p) {
    return __ldg(reinterpret_cast<const float2*>(p));
}
__device__ __forceinline__ float f2tf32f(float x) {
    uint32_t r;
    asm("cvt.rna.tf32.f32 %0, %1;" : "=r"(r) : "f"(x));
    return __uint_as_float(r);
}
__device__ __forceinline__ void mma_tf32(float* d,
    uint32_t a0, uint32_t a1, uint32_t a2, uint32_t a3,
    uint32_t b0, uint32_t b1)
{
    asm volatile(
        "mma.sync.aligned.m16n8k8.row.col.f32.tf32.tf32.f32 "
        "{%0,%1,%2,%3}, {%4,%5,%6,%7}, {%8,%9}, {%0,%1,%2,%3};"
        : "+f"(d[0]), "+f"(d[1]), "+f"(d[2]), "+f"(d[3])
        : "r"(a0), "r"(a1), "r"(a2), "r"(a3), "r"(b0), "r"(b1));
}
// per-half (256-thread) named barrier: ids 1 and 2
__device__ __forceinline__ void wbar(int half) {
    asm volatile("bar.sync %0, 256;" :: "r"(half + 1) : "memory");
}

__device__ __forceinline__ unsigned int atom_add_release(unsigned int* p, unsigned int v) {
    unsigned int r;
    asm volatile("atom.release.gpu.add.u32 %0, [%1], %2;"
                 : "=r"(r) : "l"(p), "r"(v) : "memory");
    return r;
}
__device__ __forceinline__ unsigned int ld_acquire(unsigned int* p) {
    unsigned int r;
    asm volatile("ld.acquire.gpu.u32 %0, [%1];" : "=r"(r) : "l"(p) : "memory");
    return r;
}
__device__ __forceinline__ void st_release(unsigned int* p, unsigned int v) {
    asm volatile("st.release.gpu.u32 [%0], %1;" :: "l"(p), "r"(v) : "memory");
}

// Grid barrier (R9-proven simple version)
__device__ __forceinline__ void grid_sync() {
    __syncthreads();
    if (threadIdx.x == 0) {
        unsigned int gen = ld_acquire(&g_bar_gen);
        unsigned int t = atom_add_release(&g_bar_count, 1u);
        if (t == gridDim.x - 1u) {
            g_bar_count = 0u;
            st_release(&g_bar_gen, gen + 1u);
        } else {
            while (ld_acquire(&g_bar_gen) == gen) { __nanosleep(32); }
        }
    }
    __syncthreads();
}

// ---------------------------------------------------------------------------
// Stage store: A (k-major, tf32-converted, scalar scatter) + B (k-major, f4)
// ---------------------------------------------------------------------------
__device__ __forceinline__ void stage_store(float* stage, int am, int akq,
                                            int bkk, int bnq,
                                            float4 Ar0, float4 Ar1,
                                            float4 Br0, float4 Br1)
{
    float* As = stage;
    float* Bs = stage + AS_F;
    As[(akq + 0) * AS_PITCH + am] = f2tf32f(Ar0.x);
    As[(akq + 1) * AS_PITCH + am] = f2tf32f(Ar0.y);
    As[(akq + 2) * AS_PITCH + am] = f2tf32f(Ar0.z);
    As[(akq + 3) * AS_PITCH + am] = f2tf32f(Ar0.w);
    As[(akq + 4) * AS_PITCH + am] = f2tf32f(Ar1.x);
    As[(akq + 5) * AS_PITCH + am] = f2tf32f(Ar1.y);
    As[(akq + 6) * AS_PITCH + am] = f2tf32f(Ar1.z);
    As[(akq + 7) * AS_PITCH + am] = f2tf32f(Ar1.w);
    float4 v0 = make_float4(f2tf32f(Br0.x), f2tf32f(Br0.y),
                            f2tf32f(Br0.z), f2tf32f(Br0.w));
    float4 v1 = make_float4(f2tf32f(Br1.x), f2tf32f(Br1.y),
                            f2tf32f(Br1.z), f2tf32f(Br1.w));
    *(float4*)&Bs[bkk * AS_PITCH + bnq]     = v0;
    *(float4*)&Bs[bkk * AS_PITCH + bnq + 4] = v1;
}

// ---------------------------------------------------------------------------
// GEMM core (tf32 mma.sync): acc[4][4] = A[64 x kchunk] * W[kchunk x 64]
// (R9-proven). Epilogue handled by callers.
// ---------------------------------------------------------------------------
__device__ __forceinline__ void gemm_core(int half, int ht, float* sbase,
                                          const float* __restrict__ A, int lda,
                                          const float* __restrict__ W, int N,
                                          int kchunk, float acc[4][4])
{
    const int lane = ht & 31;
    const int wrp  = ht >> 5;
    const int wm = wrp & 3;
    const int wn = wrp >> 2;
    const int g = lane >> 2;
    const int t = lane & 3;

    const int am  = ht & 63;
    const int akq = (ht >> 6) * 8;
    const int bkk = ht >> 3;
    const int bnq = (ht & 7) * 8;

    #pragma unroll
    for (int f = 0; f < 4; f++)
        #pragma unroll
        for (int i = 0; i < 4; i++) acc[f][i] = 0.0f;

    const int T = kchunk >> 5;
    const float* Abase = A + (size_t)am * lda + akq;
    const float* Wbase = W + (size_t)bkk * N + bnq;

    float4 Ar0 = ldcg4(Abase);
    float4 Ar1 = ldcg4(Abase + 4);
    float4 Br0 = ldg4(Wbase);
    float4 Br1 = ldg4(Wbase + 4);

    wbar(half);
    stage_store(sbase, am, akq, bkk, bnq, Ar0, Ar1, Br0, Br1);
    if (T > 1) {
        Ar0 = ldcg4(Abase + 32);
        Ar1 = ldcg4(Abase + 36);
        const float* wp = Wbase + 32 * N;
        Br0 = ldg4(wp);
        Br1 = ldg4(wp + 4);
    }
    wbar(half);

    int p = 0;
    for (int tt = 0; tt < T; tt++) {
        const float* As = sbase + p * STAGE_F;
        const float* Bs = As + AS_F;
        const float* Ab = As + wm * 16;
        const float* Bb = Bs + wn * 32;
        #pragma unroll
        for (int q = 0; q < 4; q++) {
            const int kr = q * 8 + t;
            uint32_t a0 = __float_as_uint(Ab[kr * AS_PITCH + g]);
            uint32_t a1 = __float_as_uint(Ab[kr * AS_PITCH + g + 8]);
            uint32_t a2 = __float_as_uint(Ab[(kr + 4) * AS_PITCH + g]);
            uint32_t a3 = __float_as_uint(Ab[(kr + 4) * AS_PITCH + g + 8]);
            #pragma unroll
            for (int f = 0; f < 4; f++) {
                uint32_t b0 = __float_as_uint(Bb[kr * AS_PITCH + f * 8 + g]);
                uint32_t b1 = __float_as_uint(Bb[(kr + 4) * AS_PITCH + f * 8 + g]);
                mma_tf32(acc[f], a0, a1, a2, a3, b0, b1);
            }
        }

        if (tt + 1 < T) {
            stage_store(sbase + (1 - p) * STAGE_F, am, akq, bkk, bnq,
                        Ar0, Ar1, Br0, Br1);
            if (tt + 2 < T) {
                int kb = (tt + 2) << 5;
                Ar0 = ldcg4(Abase + kb);
                Ar1 = ldcg4(Abase + kb + 4);
                const float* wp = Wbase + (size_t)kb * N;
                Br0 = ldg4(wp);
                Br1 = ldg4(wp + 4);
            }
            wbar(half);
            p ^= 1;
        }
    }
}

// standard GEMM tile: core + partial store
__device__ void gemm_tile(int half, int ht, float* sbase,
                          const float* __restrict__ A, int lda,
                          const float* __restrict__ W, int N,
                          float* __restrict__ Pout, int kchunk)
{
    float acc[4][4];
    gemm_core(half, ht, sbase, A, lda, W, N, kchunk, acc);

    const int lane = ht & 31;
    const int wrp  = ht >> 5;
    const int wm = wrp & 3, wn = wrp >> 2;
    const int g = lane >> 2, t = lane & 3;
    const int row0 = wm * 16 + g;
    float* r0p = Pout + (size_t)row0 * N;
    float* r1p = r0p + 8 * N;
    #pragma unroll
    for (int f = 0; f < 4; f++) {
        int col = wn * 32 + f * 8 + 2 * t;
        stcg2(r0p + col, make_float2(acc[f][0], acc[f][1]));
        stcg2(r1p + col, make_float2(acc[f][2], acc[f][3]));
    }
}

// X1 slot tables. Pairs: p0=[e1|e2], p1=[e0|e2], p2=[e0|e1]
__device__ __constant__ int D1ROW[3] = {1, 0, 0};
__device__ __constant__ int D1OFF[3] = {0, 0, 768};
__device__ __constant__ int D2ROW[3] = {2, 2, 1};
__device__ __constant__ int D2OFF[3] = {0, 768, 768};

// ---------------------------------------------------------------------------
// Gate job (fused): z=0..2 produce partials + arrive; z=3 computes in regs,
// waits for 3 arrivals, blends, scatters. Counter self-resets.
// ---------------------------------------------------------------------------
__device__ void gate_job(int half, int ht, float* sbase, int job,
                         const float* __restrict__ gateW,
                         const float* __restrict__ gateb,
                         float* __restrict__ out_final, bool last)
{
    const int ti = job % GATE_TILES;
    const int z  = job / GATE_TILES;      // 0..3
    const int m0 = (ti / 12) * 64;
    const int n0 = (ti % 12) * 64;
    const int k0 = z * 384;
    const int p  = m0 >> 6;

    if (z < 3) {
        gemm_tile(half, ht, sbase,
                  g_X2 + (size_t)m0 * KDIM + k0, KDIM,
                  gateW + (size_t)k0 * 768 + n0, 768,
                  g_pgate + (size_t)z * GATE_MN + m0 * 768 + n0, 384);
        wbar(half);                        // all partial stores issued+visible order
        if (ht == 0) atom_add_release(&g_gcnt[ti], 1u);
        return;
    }

    // consumer: own chunk in registers
    float acc[4][4];
    gemm_core(half, ht, sbase,
              g_X2 + (size_t)m0 * KDIM + k0, KDIM,
              gateW + (size_t)k0 * 768 + n0, 768, 384, acc);

    if (ht == 0) {
        while (ld_acquire(&g_gcnt[ti]) != 3u) { __nanosleep(20); }
    }
    wbar(half);

    const int lane = ht & 31;
    const int wrp  = ht >> 5;
    const int wm = wrp & 3, wn = wrp >> 2;
    const int g = lane >> 2, t = lane & 3;

    const float* P0 = g_pgate + 0 * GATE_MN + (size_t)m0 * 768 + n0;
    const float* P1 = g_pgate + 1 * GATE_MN + (size_t)m0 * 768 + n0;
    const float* P2 = g_pgate + 2 * GATE_MN + (size_t)m0 * 768 + n0;

    #pragma unroll
    for (int f = 0; f < 4; f++) {
        const int cl = wn * 32 + f * 8 + 2 * t;      // col within tile
        const int nn = n0 + cl;                      // global col 0..767
        float2 gb = ldg2(gateb + nn);
        #pragma unroll
        for (int rr = 0; rr < 2; rr++) {
            const int rl = wm * 16 + g + rr * 8;     // row within tile
            const int r  = m0 + rl;                  // global row
            const int b  = r & 63;
            float2 q0 = ldcg2(P0 + (size_t)rl * 768 + cl);
            float2 q1 = ldcg2(P1 + (size_t)rl * 768 + cl);
            float2 q2 = ldcg2(P2 + (size_t)rl * 768 + cl);
            float sx = gb.x + q0.x + q1.x + q2.x + acc[f][rr * 2 + 0];
            float sy = gb.y + q0.y + q1.y + q2.y + acc[f][rr * 2 + 1];
            float2 uv = ldcg2(g_X2 + (size_t)r * KDIM + nn);   // u (left half)
            float2 ev = ldcg2(g_e + (size_t)r * DIM + nn);
            float gx = sigmoidf(sx);
            float gy = sigmoidf(sy);
            float2 res = make_float2(gx * ev.x + (1.0f - gx) * uv.x,
                                     gy * ev.y + (1.0f - gy) * uv.y);
            if (last) {
                stcg2(out_final + (size_t)b * PREDK + p * DIM + nn, res);
            } else {
                stcg2(g_e + (size_t)r * DIM + nn, res);
                stcg2(g_X1 + (size_t)(D1ROW[p] * 64 + b) * KDIM + D1OFF[p] + nn, res);
                stcg2(g_X1 + (size_t)(D2ROW[p] * 64 + b) * KDIM + D2OFF[p] + nn, res);
            }
        }
    }
    wbar(half);                             // all reads of partials done
    if (ht == 0) st_release(&g_gcnt[ti], 0u);
}

// ---------------------------------------------------------------------------
// Maxpool phase A: job = bk*4 + seg; partial max over 128-row segment.
// Threads 0..191 each own one float4 column. No smem.
// ---------------------------------------------------------------------------
__device__ void maxpool_seg_job(int ht, int job,
                                const float* __restrict__ enc,
                                const int* __restrict__ ep)
{
    if (ht >= 192) return;
    int bk = job >> 2, seg = job & 3;
    int b = bk / 3;
    int s0 = ep[bk * 2 + 0];
    int s1 = ep[bk * 2 + 1];
    int lo = max(s0, seg * 128);
    int hi = min(s1, seg * 128 + 127);

    float4 m = make_float4(-1e30f, -1e30f, -1e30f, -1e30f);
    const float* base = enc + (size_t)b * SEQ * DIM + ht * 4;
    #pragma unroll 4
    for (int s = lo; s <= hi; s++) {
        float4 v = ldg4(base + (size_t)s * DIM);
        m.x = fmaxf(m.x, v.x); m.y = fmaxf(m.y, v.y);
        m.z = fmaxf(m.z, v.z); m.w = fmaxf(m.w, v.w);
    }
    stcg4(g_mp + (size_t)job * DIM + ht * 4, m);
}

// ---------------------------------------------------------------------------
// Maxpool phase B: combine 4 segment partials, scatter, entity score.
// ---------------------------------------------------------------------------
__device__ void maxpool_combine_job(int half, int ht, float* sb, int bk,
                                    const float* __restrict__ projW,
                                    const float* __restrict__ projb,
                                    float* __restrict__ out_score)
{
    int b = bk / 3, k = bk - b * 3;
    float dv = 0.0f;

    wbar(half);                             // protect smem from prior job
    if (ht < 192) {
        const float* mp = g_mp + (size_t)bk * 4 * DIM + ht * 4;
        float4 m0 = ldcg4(mp);
        float4 m1 = ldcg4(mp + DIM);
        float4 m2 = ldcg4(mp + 2 * DIM);
        float4 m3 = ldcg4(mp + 3 * DIM);
        float4 m;
        m.x = fmaxf(fmaxf(m0.x, m1.x), fmaxf(m2.x, m3.x));
        m.y = fmaxf(fmaxf(m0.y, m1.y), fmaxf(m2.y, m3.y));
        m.z = fmaxf(fmaxf(m0.z, m1.z), fmaxf(m2.z, m3.z));
        m.w = fmaxf(fmaxf(m0.w, m1.w), fmaxf(m2.w, m3.w));

        int d0 = ht * 4;
        stcg4(g_ent + (size_t)b * PREDK + k * DIM + d0, m);
        stcg4(g_e   + (size_t)(k * 64 + b) * DIM + d0, m);
        stcg4(g_X1  + (size_t)(D1ROW[k] * 64 + b) * KDIM + D1OFF[k] + d0, m);
        stcg4(g_X1  + (size_t)(D2ROW[k] * 64 + b) * KDIM + D2OFF[k] + d0, m);

        float4 pw = ldg4(projW + d0);
        dv = m.x * pw.x + m.y * pw.y + m.z * pw.z + m.w * pw.w;
    }
    #pragma unroll
    for (int off = 16; off > 0; off >>= 1)
        dv += __shfl_down_sync(0xffffffffu, dv, off);
    if ((ht & 31) == 0) sb[ht >> 5] = dv;    // warps 0..7 (6,7 contribute 0)
    wbar(half);
    if (ht == 0) {
        float s = sb[0] + sb[1] + sb[2] + sb[3] + sb[4] + sb[5];
        out_score[bk] = sigmoidf(s + projb[0]);
    }
    wbar(half);
}

// ---------------------------------------------------------------------------
// finish1: fc1 reduce + relu + fc2 + sigmoid + Ar + u -> X2 left; e -> X2 right
// ---------------------------------------------------------------------------
__device__ void finish1_job(int half, int t, float* sb, int r,
                            const float* __restrict__ b1,
                            const float* __restrict__ W2, const float* __restrict__ b2,
                            const float* __restrict__ ArW, const float* __restrict__ Arb)
{
    float* sh_h = sb;                  // 512
    float* red  = sb + 512;            // 5*256
    float* sh_s = sb + 512 + 1280;     // 8

    wbar(half);
    for (int j = t; j < 512; j += 256) {
        float s = b1[j];
        #pragma unroll
        for (int z = 0; z < KS_FC1; z++)
            s += __ldcg(g_pfc1 + (size_t)z * FC1_MN + r * 512 + j);
        sh_h[j] = fmaxf(s, 0.0f);
    }
    wbar(half);

    float ps[5] = {0, 0, 0, 0, 0};
    for (int j = t; j < 512; j += 256) {
        float h = sh_h[j];
        #pragma unroll
        for (int c = 0; c < 5; c++) ps[c] += h * W2[j * 5 + c];
    }
    #pragma unroll
    for (int c = 0; c < 5; c++) red[c * 256 + t] = ps[c];
    wbar(half);
    for (int off = 128; off > 0; off >>= 1) {
        if (t < off) {
            #pragma unroll
            for (int c = 0; c < 5; c++) red[c * 256 + t] += red[c * 256 + t + off];
        }
        wbar(half);
    }
    if (t < 5) sh_s[t] = sigmoidf(red[t * 256] + b2[t]);
    wbar(half);

    float s0 = sh_s[0], s1 = sh_s[1], s2 = sh_s[2], s3 = sh_s[3], s4 = sh_s[4];
    const float* epv = g_e + (size_t)r * DIM;
    float* up = g_X2 + (size_t)r * KDIM;          // u -> left half of X2
    for (int d = t; d < DIM; d += 256) {
        float a = Arb[d] + s0 * ArW[d] + s1 * ArW[DIM + d] + s2 * ArW[2 * DIM + d]
                + s3 * ArW[3 * DIM + d] + s4 * ArW[4 * DIM + d];
        float e = __ldcg(epv + d);
        __stcg(up + d, a * e);
        __stcg(up + 768 + d, e);                  // refresh X2 right half (e)
    }
}

__device__ void pred_finish_job(int half, int t, float* sb, int b,
                                const float* __restrict__ b1,
                                const float* __restrict__ W2,
                                const float* __restrict__ b2,
                                float* __restrict__ rel_out)
{
    float* sh_h = sb;
    float* red  = sb + 512;

    wbar(half);
    for (int j = t; j < 512; j += 256) {
        float s = b1[j];
        #pragma unroll
        for (int z = 0; z < KS_PRED; z++)
            s += __ldcg(g_ppred + (size_t)z * PRED_MN + b * 512 + j);
        sh_h[j] = fmaxf(s, 0.0f);
    }
    wbar(half);

    float ps[5] = {0, 0, 0, 0, 0};
    for (int j = t; j < 512; j += 256) {
        float h = sh_h[j];
        #pragma unroll
        for (int c = 0; c < 5; c++) ps[c] += h * W2[j * 5 + c];
    }
    #pragma unroll
    for (int c = 0; c < 5; c++) red[c * 256 + t] = ps[c];
    wbar(half);
    for (int off = 128; off > 0; off >>= 1) {
        if (t < off) {
            #pragma unroll
            for (int c = 0; c < 5; c++) red[c * 256 + t] += red[c * 256 + t + off];
        }
        wbar(half);
    }
    if (t < 5) rel_out[b * 5 + t] = red[t * 256] + b2[t];
}

// ---------------------------------------------------------------------------
// Persistent fused kernel: 512 threads = two 256-thread workers
// ---------------------------------------------------------------------------
__global__ void __launch_bounds__(512, 1)
fused_kernel(const float* __restrict__ enc, const int* __restrict__ ep,
             const float* __restrict__ ArW, const float* __restrict__ Arb,
             const float* __restrict__ VrW1, const float* __restrict__ Vrb1,
             const float* __restrict__ VrW2, const float* __restrict__ Vrb2,
             const float* __restrict__ gateW, const float* __restrict__ gateb,
             const float* __restrict__ predW1, const float* __restrict__ predb1,
             const float* __restrict__ predW2, const float* __restrict__ predb2,
             const float* __restrict__ projW, const float* __restrict__ projb,
             float* __restrict__ out_rel, float* __restrict__ out_score,
             float* __restrict__ out_final)
{
    extern __shared__ __align__(16) float smem_u[];

    const int half = threadIdx.x >> 8;
    const int ht   = threadIdx.x & 255;
    float* sbase = smem_u + half * WORKER_F;

    const int nb = gridDim.x;
    const int wid     = blockIdx.x * 2 + half;
    const int wstride = 2 * nb;              // 296 workers

    // ---- Phase A: span max-pool segments (768 jobs) ----
    for (int job = wid; job < 768; job += wstride)
        maxpool_seg_job(ht, job, enc, ep);
    grid_sync();

    // ---- Phase B: combine + scatter + entity scores (192 jobs) ----
    for (int job = wid; job < R192; job += wstride)
        maxpool_combine_job(half, ht, sbase, job, projW, projb, out_score);
    grid_sync();

    for (int it = 0; it < 5; it++) {
        // ---- P1: fc1 GEMM partials (288) + pred GEMM (96, iter 0) ----
        int nj = (it == 0) ? (288 + 96) : 288;
        for (int job = wid; job < nj; job += wstride) {
            if (job < 288) {
                int z = job / 24, rem = job % 24;
                int m0 = (rem >> 3) * 64, n0 = (rem & 7) * 64;
                int k0 = z * 128;
                gemm_tile(half, ht, sbase,
                          g_X1 + (size_t)m0 * KDIM + k0, KDIM,
                          VrW1 + (size_t)k0 * 512 + n0, 512,
                          g_pfc1 + (size_t)z * FC1_MN + m0 * 512 + n0, 128);
            } else {
                int j = job - 288;                 // 0..95
                int z = j >> 3, n0 = (j & 7) * 64;
                int k0 = z * 192;
                gemm_tile(half, ht, sbase,
                          g_ent + k0, PREDK,
                          predW1 + (size_t)k0 * 512 + n0, 512,
                          g_ppred + (size_t)z * PRED_MN + n0, 192);
            }
        }
        grid_sync();

        // ---- P2: fc1 finish -> u,e into X2 (+ pred finish on iter 0) ----
        nj = (it == 0) ? 256 : 192;
        for (int job = wid; job < nj; job += wstride) {
            if (job < 192) finish1_job(half, ht, sbase, job, Vrb1, VrW2, Vrb2, ArW, Arb);
            else           pred_finish_job(half, ht, sbase, job - 192,
                                           predb1, predW2, predb2, out_rel);
        }
        grid_sync();

        // ---- P3 (fused): gate GEMM + blend + scatter (144 jobs) ----
        bool last = (it == 4);
        for (int job = wid; job < 4 * GATE_TILES; job += wstride)
            gate_job(half, ht, sbase, job, gateW, gateb, out_final, last);
        if (!last) grid_sync();
    }
}

// ---------------------------------------------------------------------------
// Launcher
// ---------------------------------------------------------------------------
extern "C" void kernel_launch(void* const* d_in, const int* in_sizes, int n_in,
                              void* d_out, int out_size)
{
    const float* encoding = (const float*)d_in[0];
    const int*   ent_pos  = (const int*)  d_in[1];
    const float* Ar_W     = (const float*)d_in[2];
    const float* Ar_b     = (const float*)d_in[3];
    const float* Vr_W1    = (const float*)d_in[4];
    const float* Vr_b1    = (const float*)d_in[5];
    const float* Vr_W2    = (const float*)d_in[6];
    const float* Vr_b2    = (const float*)d_in[7];
    const float* gate_W   = (const float*)d_in[8];
    const float* gate_b   = (const float*)d_in[9];
    const float* pred_W1  = (const float*)d_in[10];
    const float* pred_b1  = (const float*)d_in[11];
    const float* pred_W2  = (const float*)d_in[12];
    const float* pred_b2  = (const float*)d_in[13];
    const float* proj_W   = (const float*)d_in[14];
    const float* proj_b   = (const float*)d_in[15];

    float* out = (float*)d_out;
    float* out_rel   = out;              // (64,5)
    float* out_score = out + 320;        // (64,3)
    float* out_final = out + 512;        // (64,3,768)

    int dev = 0;
    cudaGetDevice(&dev);
    int sms = 148;
    cudaDeviceGetAttribute(&sms, cudaDevAttrMultiProcessorCount, dev);

    cudaFuncSetAttribute(fused_kernel,
                         cudaFuncAttributeMaxDynamicSharedMemorySize,
                         TOTAL_SMEM_B);

    fused_kernel<<<sms, 512, TOTAL_SMEM_B>>>(
        encoding, ent_pos, Ar_W, Ar_b,
        Vr_W1, Vr_b1, Vr_W2, Vr_b2,
        gate_W, gate_b,
        pred_W1, pred_b1, pred_W2, pred_b2,
        proj_W, proj_b,
        out_rel, out_score, out_final);

    (void)in_sizes; (void)n_in; (void)out_size;
}

// round 12
// speedup vs baseline: 1.6093x; 1.6093x over previous
#include <cuda_runtime.h>
#include <cstdint>

// ---------------------------------------------------------------------------
// Problem constants
// ---------------------------------------------------------------------------
#define BATCH 64
#define SEQ   512
#define DIM   768
#define BD    (BATCH * DIM)          // 49152
#define R192  192
#define KDIM  1536
#define PREDK 2304

#define KS_FC1  12                   // 1536 = 12 * 128
#define KS_GATE 8                    // 1536 = 8 * 192
#define KS_PRED 12                   // 2304 = 12 * 192

#define FC1_MN  (R192 * 512)         // 98304
#define GATE_MN (R192 * 768)         // 147456
#define PRED_MN (BATCH * 512)        // 32768

// smem: 2 stages x (As[32][72] + Bs[32][72]) floats = 36864 B (static)
#define AS_PITCH 72
#define AS_F     (32 * AS_PITCH)     // 2304
#define STAGE_F  (2 * AS_F)          // 4608

// ---------------------------------------------------------------------------
// Device scratch
// ---------------------------------------------------------------------------
__device__ float g_ent  [BATCH * PREDK];
__device__ float g_e    [3 * BD];              // entity state [r][d], r=k*64+b
__device__ float g_X1   [R192 * KDIM];         // fc1 input  [eA | eB]
__device__ float g_X2   [R192 * KDIM];         // gate input [u  | e ]
__device__ float g_mp   [768 * DIM];           // maxpool segment partials
__device__ float g_pfc1 [KS_FC1  * FC1_MN];
__device__ float g_pgate[KS_GATE * GATE_MN];
__device__ float g_ppred[KS_PRED * PRED_MN];

// ---------------------------------------------------------------------------
// Helpers
// ---------------------------------------------------------------------------
__device__ __forceinline__ float sigmoidf(float x) {
    return 1.0f / (1.0f + expf(-x));
}
__device__ __forceinline__ float4 ldg4(const float* p) {
    return __ldg(reinterpret_cast<const float4*>(p));
}
__device__ __forceinline__ float f2tf32f(float x) {
    uint32_t r;
    asm("cvt.rna.tf32.f32 %0, %1;" : "=r"(r) : "f"(x));
    return __uint_as_float(r);
}
__device__ __forceinline__ void mma_tf32(float* d,
    uint32_t a0, uint32_t a1, uint32_t a2, uint32_t a3,
    uint32_t b0, uint32_t b1)
{
    asm volatile(
        "mma.sync.aligned.m16n8k8.row.col.f32.tf32.tf32.f32 "
        "{%0,%1,%2,%3}, {%4,%5,%6,%7}, {%8,%9}, {%0,%1,%2,%3};"
        : "+f"(d[0]), "+f"(d[1]), "+f"(d[2]), "+f"(d[3])
        : "r"(a0), "r"(a1), "r"(a2), "r"(a3), "r"(b0), "r"(b1));
}

// X1 slot tables. Pairs: p0=[e1|e2], p1=[e0|e2], p2=[e0|e1]
__device__ __constant__ int D1ROW[3] = {1, 0, 0};
__device__ __constant__ int D1OFF[3] = {0, 0, 768};
__device__ __constant__ int D2ROW[3] = {2, 2, 1};
__device__ __constant__ int D2OFF[3] = {0, 768, 768};

// ---------------------------------------------------------------------------
// Stage store: A (k-major, tf32-converted, scalar scatter) + B (k-major, f4)
// ---------------------------------------------------------------------------
__device__ __forceinline__ void stage_store(float* stage, int am, int akq,
                                            int bkk, int bnq,
                                            float4 Ar0, float4 Ar1,
                                            float4 Br0, float4 Br1)
{
    float* As = stage;
    float* Bs = stage + AS_F;
    As[(akq + 0) * AS_PITCH + am] = f2tf32f(Ar0.x);
    As[(akq + 1) * AS_PITCH + am] = f2tf32f(Ar0.y);
    As[(akq + 2) * AS_PITCH + am] = f2tf32f(Ar0.z);
    As[(akq + 3) * AS_PITCH + am] = f2tf32f(Ar0.w);
    As[(akq + 4) * AS_PITCH + am] = f2tf32f(Ar1.x);
    As[(akq + 5) * AS_PITCH + am] = f2tf32f(Ar1.y);
    As[(akq + 6) * AS_PITCH + am] = f2tf32f(Ar1.z);
    As[(akq + 7) * AS_PITCH + am] = f2tf32f(Ar1.w);
    float4 v0 = make_float4(f2tf32f(Br0.x), f2tf32f(Br0.y),
                            f2tf32f(Br0.z), f2tf32f(Br0.w));
    float4 v1 = make_float4(f2tf32f(Br1.x), f2tf32f(Br1.y),
                            f2tf32f(Br1.z), f2tf32f(Br1.w));
    *(float4*)&Bs[bkk * AS_PITCH + bnq]     = v0;
    *(float4*)&Bs[bkk * AS_PITCH + bnq + 4] = v1;
}

// ---------------------------------------------------------------------------
// GEMM tile (one 256-thread block per job): C[64x64] = A[64xK] * W[Kx64-of-N]
// R9-proven tf32 mma pipeline; one job per block so no smem-reuse guard.
// ---------------------------------------------------------------------------
__device__ __forceinline__ void gemm_tile_blk(float* sbase,
                          const float* __restrict__ A, int lda,
                          const float* __restrict__ W, int N,
                          float* __restrict__ Pout, int kchunk)
{
    const int ht = threadIdx.x;
    const int lane = ht & 31;
    const int wrp  = ht >> 5;
    const int wm = wrp & 3;
    const int wn = wrp >> 2;
    const int g = lane >> 2;
    const int t = lane & 3;

    const int am  = ht & 63;
    const int akq = (ht >> 6) * 8;
    const int bkk = ht >> 3;
    const int bnq = (ht & 7) * 8;

    float acc[4][4];
    #pragma unroll
    for (int f = 0; f < 4; f++)
        #pragma unroll
        for (int i = 0; i < 4; i++) acc[f][i] = 0.0f;

    const int T = kchunk >> 5;
    const float* Abase = A + (size_t)am * lda + akq;
    const float* Wbase = W + (size_t)bkk * N + bnq;

    float4 Ar0 = *(const float4*)(Abase);
    float4 Ar1 = *(const float4*)(Abase + 4);
    float4 Br0 = ldg4(Wbase);
    float4 Br1 = ldg4(Wbase + 4);

    stage_store(sbase, am, akq, bkk, bnq, Ar0, Ar1, Br0, Br1);
    if (T > 1) {
        Ar0 = *(const float4*)(Abase + 32);
        Ar1 = *(const float4*)(Abase + 36);
        const float* wp = Wbase + 32 * N;
        Br0 = ldg4(wp);
        Br1 = ldg4(wp + 4);
    }
    __syncthreads();

    int p = 0;
    for (int tt = 0; tt < T; tt++) {
        const float* As = sbase + p * STAGE_F;
        const float* Bs = As + AS_F;
        const float* Ab = As + wm * 16;
        const float* Bb = Bs + wn * 32;
        #pragma unroll
        for (int q = 0; q < 4; q++) {
            const int kr = q * 8 + t;
            uint32_t a0 = __float_as_uint(Ab[kr * AS_PITCH + g]);
            uint32_t a1 = __float_as_uint(Ab[kr * AS_PITCH + g + 8]);
            uint32_t a2 = __float_as_uint(Ab[(kr + 4) * AS_PITCH + g]);
            uint32_t a3 = __float_as_uint(Ab[(kr + 4) * AS_PITCH + g + 8]);
            #pragma unroll
            for (int f = 0; f < 4; f++) {
                uint32_t b0 = __float_as_uint(Bb[kr * AS_PITCH + f * 8 + g]);
                uint32_t b1 = __float_as_uint(Bb[(kr + 4) * AS_PITCH + f * 8 + g]);
                mma_tf32(acc[f], a0, a1, a2, a3, b0, b1);
            }
        }

        if (tt + 1 < T) {
            stage_store(sbase + (1 - p) * STAGE_F, am, akq, bkk, bnq,
                        Ar0, Ar1, Br0, Br1);
            if (tt + 2 < T) {
                int kb = (tt + 2) << 5;
                Ar0 = *(const float4*)(Abase + kb);
                Ar1 = *(const float4*)(Abase + kb + 4);
                const float* wp = Wbase + (size_t)kb * N;
                Br0 = ldg4(wp);
                Br1 = ldg4(wp + 4);
            }
            __syncthreads();
            p ^= 1;
        }
    }

    const int row0 = wm * 16 + g;
    float* r0p = Pout + (size_t)row0 * N;
    float* r1p = r0p + 8 * N;
    #pragma unroll
    for (int f = 0; f < 4; f++) {
        int col = wn * 32 + f * 8 + 2 * t;
        *(float2*)(r0p + col) = make_float2(acc[f][0], acc[f][1]);
        *(float2*)(r1p + col) = make_float2(acc[f][2], acc[f][3]);
    }
}

// ---------------------------------------------------------------------------
// Kernel: maxpool segments. block = bk*4 + seg; threads 0..191 own f4 cols.
// ---------------------------------------------------------------------------
__global__ void __launch_bounds__(256)
maxpool_seg_kernel(const float* __restrict__ enc, const int* __restrict__ ep)
{
    int ht = threadIdx.x;
    if (ht >= 192) return;
    int job = blockIdx.x;
    int bk = job >> 2, seg = job & 3;
    int b = bk / 3;
    int s0 = ep[bk * 2 + 0];
    int s1 = ep[bk * 2 + 1];
    int lo = max(s0, seg * 128);
    int hi = min(s1, seg * 128 + 127);

    float4 m = make_float4(-1e30f, -1e30f, -1e30f, -1e30f);
    const float* base = enc + (size_t)b * SEQ * DIM + ht * 4;
    #pragma unroll 4
    for (int s = lo; s <= hi; s++) {
        float4 v = ldg4(base + (size_t)s * DIM);
        m.x = fmaxf(m.x, v.x); m.y = fmaxf(m.y, v.y);
        m.z = fmaxf(m.z, v.z); m.w = fmaxf(m.w, v.w);
    }
    *(float4*)(g_mp + (size_t)job * DIM + ht * 4) = m;
}

// ---------------------------------------------------------------------------
// Kernel: maxpool combine + scatter + entity score. block = bk.
// ---------------------------------------------------------------------------
__global__ void __launch_bounds__(256)
maxpool_combine_kernel(const float* __restrict__ projW,
                       const float* __restrict__ projb,
                       float* __restrict__ out_score)
{
    __shared__ float red[8];
    int ht = threadIdx.x;
    int bk = blockIdx.x;
    int b = bk / 3, k = bk - b * 3;
    float dv = 0.0f;

    if (ht < 192) {
        const float* mp = g_mp + (size_t)bk * 4 * DIM + ht * 4;
        float4 m0 = *(const float4*)(mp);
        float4 m1 = *(const float4*)(mp + DIM);
        float4 m2 = *(const float4*)(mp + 2 * DIM);
        float4 m3 = *(const float4*)(mp + 3 * DIM);
        float4 m;
        m.x = fmaxf(fmaxf(m0.x, m1.x), fmaxf(m2.x, m3.x));
        m.y = fmaxf(fmaxf(m0.y, m1.y), fmaxf(m2.y, m3.y));
        m.z = fmaxf(fmaxf(m0.z, m1.z), fmaxf(m2.z, m3.z));
        m.w = fmaxf(fmaxf(m0.w, m1.w), fmaxf(m2.w, m3.w));

        int d0 = ht * 4;
        *(float4*)(g_ent + (size_t)b * PREDK + k * DIM + d0) = m;
        *(float4*)(g_e   + (size_t)(k * 64 + b) * DIM + d0) = m;
        *(float4*)(g_X1  + (size_t)(D1ROW[k] * 64 + b) * KDIM + D1OFF[k] + d0) = m;
        *(float4*)(g_X1  + (size_t)(D2ROW[k] * 64 + b) * KDIM + D2OFF[k] + d0) = m;
        *(float4*)(g_X2  + (size_t)(k * 64 + b) * KDIM + 768 + d0) = m;

        float4 pw = ldg4(projW + d0);
        dv = m.x * pw.x + m.y * pw.y + m.z * pw.z + m.w * pw.w;
    }
    #pragma unroll
    for (int off = 16; off > 0; off >>= 1)
        dv += __shfl_down_sync(0xffffffffu, dv, off);
    if ((ht & 31) == 0) red[ht >> 5] = dv;
    __syncthreads();
    if (ht == 0) {
        float s = red[0] + red[1] + red[2] + red[3] + red[4] + red[5];
        out_score[bk] = sigmoidf(s + projb[0]);
    }
}

// ---------------------------------------------------------------------------
// Kernel: fc1 GEMM partials (blocks 0..287) + pred GEMM (288..383, iter 0)
// ---------------------------------------------------------------------------
__global__ void __launch_bounds__(256)
fc1_gemm_kernel(const float* __restrict__ VrW1, const float* __restrict__ predW1)
{
    __shared__ __align__(16) float sbase[2 * STAGE_F];
    int job = blockIdx.x;
    if (job < 288) {
        int z = job / 24, rem = job % 24;
        int m0 = (rem >> 3) * 64, n0 = (rem & 7) * 64;
        int k0 = z * 128;
        gemm_tile_blk(sbase,
                      g_X1 + (size_t)m0 * KDIM + k0, KDIM,
                      VrW1 + (size_t)k0 * 512 + n0, 512,
                      g_pfc1 + (size_t)z * FC1_MN + m0 * 512 + n0, 128);
    } else {
        int j = job - 288;                 // 0..95
        int z = j >> 3, n0 = (j & 7) * 64;
        int k0 = z * 192;
        gemm_tile_blk(sbase,
                      g_ent + k0, PREDK,
                      predW1 + (size_t)k0 * 512 + n0, 512,
                      g_ppred + (size_t)z * PRED_MN + n0, 192);
    }
}

// ---------------------------------------------------------------------------
// Kernel: gate GEMM partials (288 blocks)
// ---------------------------------------------------------------------------
__global__ void __launch_bounds__(256)
gate_gemm_kernel(const float* __restrict__ gateW)
{
    __shared__ __align__(16) float sbase[2 * STAGE_F];
    int job = blockIdx.x;
    int z = job / 36, rem = job % 36;
    int m0 = (rem / 12) * 64, n0 = (rem % 12) * 64;
    int k0 = z * 192;
    gemm_tile_blk(sbase,
                  g_X2 + (size_t)m0 * KDIM + k0, KDIM,
                  gateW + (size_t)k0 * 768 + n0, 768,
                  g_pgate + (size_t)z * GATE_MN + m0 * 768 + n0, 192);
}

// ---------------------------------------------------------------------------
// Kernel: finish1 (blocks 0..191) + pred finish (192..255, iter 0)
// ---------------------------------------------------------------------------
__global__ void __launch_bounds__(256)
finish_kernel(const float* __restrict__ b1, const float* __restrict__ W2,
              const float* __restrict__ b2, const float* __restrict__ ArW,
              const float* __restrict__ Arb,
              const float* __restrict__ pb1, const float* __restrict__ pW2,
              const float* __restrict__ pb2, float* __restrict__ rel_out)
{
    __shared__ float sh_h[512];
    __shared__ float red[5 * 256];
    __shared__ float sh_s[8];
    int t = threadIdx.x;
    int blk = blockIdx.x;

    if (blk < 192) {
        int r = blk;
        for (int j = t; j < 512; j += 256) {
            float s = b1[j];
            #pragma unroll
            for (int z = 0; z < KS_FC1; z++)
                s += g_pfc1[(size_t)z * FC1_MN + r * 512 + j];
            sh_h[j] = fmaxf(s, 0.0f);
        }
        __syncthreads();

        float ps[5] = {0, 0, 0, 0, 0};
        for (int j = t; j < 512; j += 256) {
            float h = sh_h[j];
            #pragma unroll
            for (int c = 0; c < 5; c++) ps[c] += h * W2[j * 5 + c];
        }
        #pragma unroll
        for (int c = 0; c < 5; c++) red[c * 256 + t] = ps[c];
        __syncthreads();
        for (int off = 128; off > 0; off >>= 1) {
            if (t < off) {
                #pragma unroll
                for (int c = 0; c < 5; c++) red[c * 256 + t] += red[c * 256 + t + off];
            }
            __syncthreads();
        }
        if (t < 5) sh_s[t] = sigmoidf(red[t * 256] + b2[t]);
        __syncthreads();

        float s0 = sh_s[0], s1 = sh_s[1], s2 = sh_s[2], s3 = sh_s[3], s4 = sh_s[4];
        const float* epv = g_e + (size_t)r * DIM;
        float* up = g_X2 + (size_t)r * KDIM;          // u -> left half of X2
        for (int d = t; d < DIM; d += 256) {
            float a = Arb[d] + s0 * ArW[d] + s1 * ArW[DIM + d] + s2 * ArW[2 * DIM + d]
                    + s3 * ArW[3 * DIM + d] + s4 * ArW[4 * DIM + d];
            up[d] = a * epv[d];
        }
    } else {
        int b = blk - 192;
        for (int j = t; j < 512; j += 256) {
            float s = pb1[j];
            #pragma unroll
            for (int z = 0; z < KS_PRED; z++)
                s += g_ppred[(size_t)z * PRED_MN + b * 512 + j];
            sh_h[j] = fmaxf(s, 0.0f);
        }
        __syncthreads();

        float ps[5] = {0, 0, 0, 0, 0};
        for (int j = t; j < 512; j += 256) {
            float h = sh_h[j];
            #pragma unroll
            for (int c = 0; c < 5; c++) ps[c] += h * pW2[j * 5 + c];
        }
        #pragma unroll
        for (int c = 0; c < 5; c++) red[c * 256 + t] = ps[c];
        __syncthreads();
        for (int off = 128; off > 0; off >>= 1) {
            if (t < off) {
                #pragma unroll
                for (int c = 0; c < 5; c++) red[c * 256 + t] += red[c * 256 + t + off];
            }
            __syncthreads();
        }
        if (t < 5) rel_out[b * 5 + t] = red[t * 256] + pb2[t];
    }
}

// ---------------------------------------------------------------------------
// Kernel: gate blend (144 blocks x 256 threads; one float4 each)
// ---------------------------------------------------------------------------
__global__ void __launch_bounds__(256)
blend_kernel(const float* __restrict__ gateb, float* __restrict__ out_final,
             int last)
{
    int q = blockIdx.x * 256 + threadIdx.x;      // < 36864
    int idx = q * 4;
    int r = idx / 768, n = idx - r * 768;
    int p = r >> 6, b = r & 63;
    float4 s = *(const float4*)(gateb + n);
    #pragma unroll
    for (int z = 0; z < KS_GATE; z++) {
        float4 pv = *(const float4*)(g_pgate + (size_t)z * GATE_MN + idx);
        s.x += pv.x; s.y += pv.y; s.z += pv.z; s.w += pv.w;
    }
    float4 uv = *(const float4*)(g_X2 + (size_t)r * KDIM + n);   // u
    float4 ev = *(const float4*)(g_e + idx);
    float4 res; float gg;
    gg = sigmoidf(s.x); res.x = gg * ev.x + (1.0f - gg) * uv.x;
    gg = sigmoidf(s.y); res.y = gg * ev.y + (1.0f - gg) * uv.y;
    gg = sigmoidf(s.z); res.z = gg * ev.z + (1.0f - gg) * uv.z;
    gg = sigmoidf(s.w); res.w = gg * ev.w + (1.0f - gg) * uv.w;
    if (last) {
        *(float4*)(out_final + (size_t)b * PREDK + p * DIM + n) = res;
    } else {
        *(float4*)(g_e + idx) = res;
        *(float4*)(g_X2 + (size_t)r * KDIM + 768 + n) = res;
        *(float4*)(g_X1 + (size_t)(D1ROW[p] * 64 + b) * KDIM + D1OFF[p] + n) = res;
        *(float4*)(g_X1 + (size_t)(D2ROW[p] * 64 + b) * KDIM + D2OFF[p] + n) = res;
    }
}

// ---------------------------------------------------------------------------
// Launcher: 22 kernel launches, graph-capturable, no allocations
// ---------------------------------------------------------------------------
extern "C" void kernel_launch(void* const* d_in, const int* in_sizes, int n_in,
                              void* d_out, int out_size)
{
    const float* encoding = (const float*)d_in[0];
    const int*   ent_pos  = (const int*)  d_in[1];
    const float* Ar_W     = (const float*)d_in[2];
    const float* Ar_b     = (const float*)d_in[3];
    const float* Vr_W1    = (const float*)d_in[4];
    const float* Vr_b1    = (const float*)d_in[5];
    const float* Vr_W2    = (const float*)d_in[6];
    const float* Vr_b2    = (const float*)d_in[7];
    const float* gate_W   = (const float*)d_in[8];
    const float* gate_b   = (const float*)d_in[9];
    const float* pred_W1  = (const float*)d_in[10];
    const float* pred_b1  = (const float*)d_in[11];
    const float* pred_W2  = (const float*)d_in[12];
    const float* pred_b2  = (const float*)d_in[13];
    const float* proj_W   = (const float*)d_in[14];
    const float* proj_b   = (const float*)d_in[15];

    float* out = (float*)d_out;
    float* out_rel   = out;              // (64,5)
    float* out_score = out + 320;        // (64,3)
    float* out_final = out + 512;        // (64,3,768)

    maxpool_seg_kernel<<<768, 256>>>(encoding, ent_pos);
    maxpool_combine_kernel<<<192, 256>>>(proj_W, proj_b, out_score);

    for (int it = 0; it < 5; it++) {
        int g1 = (it == 0) ? 384 : 288;
        fc1_gemm_kernel<<<g1, 256>>>(Vr_W1, pred_W1);
        int g2 = (it == 0) ? 256 : 192;
        finish_kernel<<<g2, 256>>>(Vr_b1, Vr_W2, Vr_b2, Ar_W, Ar_b,
                                   pred_b1, pred_W2, pred_b2, out_rel);
        gate_gemm_kernel<<<288, 256>>>(gate_W);
        blend_kernel<<<144, 256>>>(gate_b, out_final, (it == 4) ? 1 : 0);
    }

    (void)in_sizes; (void)n_in; (void)out_size;
}